// round 10
// baseline (speedup 1.0000x reference)
#include <cuda_runtime.h>
#include <cstdint>

#define TT   512
#define BB   128
#define II   256
#define HH   512
#define HXX  768
#define NCTA 128      // one CTA per 4 H-columns; all co-resident
#define JPC  4
#define GCN  16       // gate-cols per CTA
#define NTHR 256      // 8 warps; warp w = k-slice w (96 k each)
#define KG   8
#define KPG  96
#define KCW  16       // k window per staged iteration (6 iterations)
#define WROW 772      // padded weight row
#define VROW 20       // 16 + 4 pad floats -> 80B row, conflict-free
#define VS_ELEMS (KG * BB * VROW)       // 20480 floats per buffer
#define WS_ELEMS (GCN * WROW)           // 12352 floats
#define SMEM_BYTES ((WS_ELEMS + 2 * VS_ELEMS) * 4)   // 213248 B

__device__ float    g_C[BB * HH];
__device__ float    g_Wpack[4 * HH * HXX];   // [g][j][k], k contiguous
__device__ unsigned g_bar;

#define FMA2(acc, a, b) \
    asm("fma.rn.f32x2 %0, %1, %2, %0;" : "+l"(acc) : "l"(a), "l"(b))

#define CP16(dst, src, sz) \
    asm volatile("cp.async.cg.shared.global [%0], [%1], 16, %2;" \
                 :: "r"(dst), "l"(src), "r"(sz) : "memory")

__device__ __forceinline__ float fsigm(float x) {
    float e; asm("ex2.approx.f32 %0, %1;" : "=f"(e) : "f"(-1.4426950408889634f * x));
    float r; asm("rcp.approx.f32 %0, %1;" : "=f"(r) : "f"(1.0f + e));
    return r;
}
__device__ __forceinline__ float ftanh(float x) {
    float ax = fabsf(x);
    float e; asm("ex2.approx.f32 %0, %1;" : "=f"(e) : "f"(-2.885390081777927f * ax));
    float r; asm("rcp.approx.f32 %0, %1;" : "=f"(r) : "f"(1.0f + e));
    return copysignf((1.0f - e) * r, x);
}

// ---------------------------------------------------------------------------
__global__ void pack_weights(const float* __restrict__ Wf, const float* __restrict__ Wi,
                             const float* __restrict__ Wc, const float* __restrict__ Wo) {
    if (blockIdx.x == 0 && blockIdx.y == 0 && blockIdx.z == 0 &&
        threadIdx.x == 0 && threadIdx.y == 0) g_bar = 0u;
    __shared__ float tile[32][33];
    const int g  = blockIdx.z;
    const float* W = (g == 0) ? Wf : (g == 1) ? Wi : (g == 2) ? Wc : Wo;
    const int j0 = blockIdx.x * 32;
    const int k0 = blockIdx.y * 32;
    const int tx = threadIdx.x, ty0 = threadIdx.y;
    #pragma unroll
    for (int ty = ty0; ty < 32; ty += 8)
        tile[ty][tx] = W[(size_t)(k0 + ty) * HH + (j0 + tx)];
    __syncthreads();
    #pragma unroll
    for (int ty = ty0; ty < 32; ty += 8)
        g_Wpack[(size_t)(g * HH + j0 + ty) * HXX + (k0 + tx)] = tile[tx][ty];
}

// ---------------------------------------------------------------------------
// Stage iteration i via cp.async.cg (L2-direct). For kg, window k0 = kg*96+i*16.
// Windows are 16-aligned and never straddle the h/x boundary at k=512.
// 4096 float4 total / 256 threads = 16 each.
// ---------------------------------------------------------------------------
__device__ __forceinline__ void stage(uint32_t vdst, const float* __restrict__ x,
                                      const float* __restrict__ out, int t, int i, int tid) {
    #pragma unroll
    for (int j = 0; j < 16; j++) {
        const int idx = tid + j * NTHR;        // 0..4095
        const int kgw = idx >> 9;              // 8 kg slices
        const int rem = idx & 511;
        const int b   = rem >> 2;
        const int q   = rem & 3;
        const int k0  = kgw * KPG + i * KCW;
        const uint32_t d = vdst + (uint32_t)(((kgw * BB + b) * VROW + q * 4) * 4);
        const float* s;
        int sz = 16;
        if (k0 < 512) {
            if (t == 0) { s = x; sz = 0; }     // zero-fill, dummy valid src
            else s = out + (size_t)(t - 1) * (BB * HH) + (size_t)b * HH + k0 + q * 4;
        } else {
            s = x + (size_t)t * (BB * II) + (size_t)b * II + (k0 - 512) + q * 4;
        }
        CP16(d, s, sz);
    }
}

// ---------------------------------------------------------------------------
// Persistent kernel. warp = kg (k-slice of 96). lane: gcg = lane&1 (gate-col
// group), bg = lane>>1. Thread tile: 8 gc (gc = gcg + 2*gi) x 8 b (b = bi*16+bg).
// ---------------------------------------------------------------------------
__global__ void __launch_bounds__(NTHR, 1)
lstm_persist(const float* __restrict__ x,
             const float* __restrict__ bf, const float* __restrict__ bi_,
             const float* __restrict__ bc, const float* __restrict__ bo,
             float* out)
{
    extern __shared__ float sm[];
    float* Ws  = sm;                 // [GCN][WROW]
    float* vsm = sm + WS_ELEMS;      // 2 x [KG][BB][VROW]
    const uint32_t vsm_s = (uint32_t)__cvta_generic_to_shared(vsm);

    const int tid  = threadIdx.x;
    const int cid  = blockIdx.x;
    const int j0   = cid * JPC;
    const int kg   = tid >> 5;
    const int lane = tid & 31;
    const int gcg  = lane & 1;
    const int bg   = lane >> 1;

    // Stage 16 weight columns once (49KB), coalesced.
    {
        const float4* wp = (const float4*)g_Wpack;
        #pragma unroll
        for (int it = 0; it < (GCN * (HXX / 4)) / NTHR; ++it) {   // 12 iters
            const int idx = tid + it * NTHR;
            const int gc  = idx / (HXX / 4);
            const int k4  = idx % (HXX / 4);
            const int g = gc >> 2, jj = gc & 3;
            *(float4*)(Ws + gc * WROW + k4 * 4) =
                wp[(size_t)(g * HH + j0 + jj) * (HXX / 4) + k4];
        }
    }

    // Bias (added only in kg==0 accumulators). gc = gcg + 2*gi.
    unsigned long long ub[8];
    #pragma unroll
    for (int gi = 0; gi < 8; gi++) {
        const int gc = gcg + 2 * gi;
        const int g = gc >> 2, jj = gc & 3;
        const float* bp = (g == 0) ? bf : (g == 1) ? bi_ : (g == 2) ? bc : bo;
        ub[gi] = (kg == 0) ? (unsigned long long)__float_as_uint(bp[j0 + jj]) : 0ull;
    }
    __syncthreads();

    const float* wthr = Ws + gcg * WROW + kg * KPG;       // +gi*2*WROW, +i*16+kk
    const float* vthr = vsm + (kg * BB + bg) * VROW;      // +buf*VS, +bi*16*VROW, +kk

    for (int t = 0; t < TT; ++t) {
        unsigned long long acc[8][8];
        #pragma unroll
        for (int gi = 0; gi < 8; gi++)
            #pragma unroll
            for (int bi = 0; bi < 8; bi++) acc[gi][bi] = ub[gi];

        stage(vsm_s, x, out, t, 0, tid);
        asm volatile("cp.async.commit_group;");
        asm volatile("cp.async.wait_group 0;" ::: "memory");
        __syncthreads();

        #pragma unroll 1
        for (int i = 0; i < 6; ++i) {
            const int buf = i & 1;
            if (i < 5) {
                stage(vsm_s + (uint32_t)((buf ^ 1) * VS_ELEMS * 4), x, out, t, i + 1, tid);
                asm volatile("cp.async.commit_group;");
            }
            const float* wr = wthr + i * KCW;
            const float* vb = vthr + buf * VS_ELEMS;

            #pragma unroll
            for (int kk = 0; kk < KCW; kk += 4) {
                ulonglong2 v[8];
                #pragma unroll
                for (int bi = 0; bi < 8; bi++)
                    v[bi] = *(const ulonglong2*)(vb + bi * (16 * VROW) + kk);
                #pragma unroll
                for (int gi = 0; gi < 8; gi++) {
                    const ulonglong2 w = *(const ulonglong2*)(wr + gi * (2 * WROW) + kk);
                    #pragma unroll
                    for (int bi = 0; bi < 8; bi++) {
                        FMA2(acc[gi][bi], w.x, v[bi].x);
                        FMA2(acc[gi][bi], w.y, v[bi].y);
                    }
                }
            }
            if (i < 5) {
                asm volatile("cp.async.wait_group 0;" ::: "memory");
                __syncthreads();
            }
        }

        // kg-partial exchange in buffer-0 region (last compute read buffer 1).
        float* gsm = vsm;   // [kg 8][gc 16][b 128] = 64KB
        #pragma unroll
        for (int gi = 0; gi < 8; gi++) {
            const int gc = gcg + 2 * gi;
            #pragma unroll
            for (int bi = 0; bi < 8; bi++) {
                const unsigned long long a = acc[gi][bi];
                const float lo = __uint_as_float((unsigned)(a & 0xffffffffu));
                const float hi = __uint_as_float((unsigned)(a >> 32));
                gsm[(kg * GCN + gc) * BB + (bi * 16 + bg)] = lo + hi;
            }
        }
        __syncthreads();

        // Elementwise update: 512 cells/CTA, 2 per thread; reduce 8 kg partials.
        #pragma unroll
        for (int e = 0; e < 2; e++) {
            const int cell = tid + e * NTHR;
            const int b = cell & 127, jj = cell >> 7;
            float gate[4];
            #pragma unroll
            for (int gi = 0; gi < 4; gi++) {
                float s = 0.f;
                #pragma unroll
                for (int k = 0; k < KG; k++)
                    s += gsm[(k * GCN + gi * 4 + jj) * BB + b];
                gate[gi] = s;
            }
            const float fs = fsigm(gate[0]);
            const float is = fsigm(gate[1]);
            const float os = fsigm(gate[3]);
            const float Cold = (t == 0) ? 0.0f : g_C[b * HH + j0 + jj];
            const float Cnew = fs * Cold + is * ftanh(gate[2]);
            g_C[b * HH + j0 + jj] = Cnew;
            out[(size_t)t * (BB * HH) + (size_t)b * HH + j0 + jj] = os * ftanh(Cnew);
        }

        // Grid barrier (release add / acquire poll). All 128 CTAs resident.
        if (t < TT - 1) {
            __syncthreads();
            if (tid == 0) {
                asm volatile("red.release.gpu.global.add.u32 [%0], %1;"
                             :: "l"(&g_bar), "r"(1u) : "memory");
                const unsigned target = (unsigned)NCTA * (unsigned)(t + 1);
                unsigned v;
                do {
                    asm volatile("ld.acquire.gpu.global.u32 %0, [%1];"
                                 : "=r"(v) : "l"(&g_bar) : "memory");
                } while (v < target);
            }
            __syncthreads();
        }
    }
}

// ---------------------------------------------------------------------------
extern "C" void kernel_launch(void* const* d_in, const int* in_sizes, int n_in,
                              void* d_out, int out_size) {
    (void)in_sizes; (void)n_in; (void)out_size;
    const float* x  = (const float*)d_in[0];
    const float* Wf = (const float*)d_in[1];
    const float* bf = (const float*)d_in[2];
    const float* Wi = (const float*)d_in[3];
    const float* bi = (const float*)d_in[4];
    const float* Wc = (const float*)d_in[5];
    const float* bc = (const float*)d_in[6];
    const float* Wo = (const float*)d_in[7];
    const float* bo = (const float*)d_in[8];
    float* out = (float*)d_out;

    cudaFuncSetAttribute(lstm_persist, cudaFuncAttributeMaxDynamicSharedMemorySize, SMEM_BYTES);

    pack_weights<<<dim3(HH / 32, HXX / 32, 4), dim3(32, 8)>>>(Wf, Wi, Wc, Wo);
    lstm_persist<<<NCTA, NTHR, SMEM_BYTES>>>(x, bf, bi, bc, bo, out);
}

// round 11
// speedup vs baseline: 1.3101x; 1.3101x over previous
#include <cuda_runtime.h>
#include <cstdint>

#define TT   512
#define BB   128
#define II   256
#define HH   512
#define HXX  768
#define NCTA 128      // one CTA per 4 H-columns; all co-resident (<=148 SMs)
#define JPC  4
#define GCN  16       // gate-cols per CTA (4 gates * 4 cols)
#define NTHR 512      // 4 k-groups x 128 threads
#define KG   4
#define KPG  192      // k per group
#define KC   32       // k window per iteration (6 iterations)
#define WROW 772      // padded weight row: tx*772 words -> banks {0,4,8,12}, conflict-free
#define VROW 36       // padded v row: ty*36 words -> full bank coverage, conflict-free
#define VS_ELEMS (KG * BB * VROW)       // 18432 floats per buffer
#define WS_ELEMS (GCN * WROW)           // 12352 floats
#define SMEM_BYTES ((WS_ELEMS + 2 * VS_ELEMS) * 4)   // 196864 B

__device__ float    g_C[BB * HH];
__device__ float    g_Wpack[4 * HH * HXX];   // [g][j][k], k contiguous
__device__ unsigned g_bar;

// f32x2 packed FMA (FFMA2): 2 MACs/instr.
#define FMA2(acc, a, b) \
    asm("fma.rn.f32x2 %0, %1, %2, %0;" : "+l"(acc) : "l"(a), "l"(b))

// 16B async copy, L2-direct (.cg). sz=0 -> zero-fill destination.
#define CP16(dst, src, sz) \
    asm volatile("cp.async.cg.shared.global [%0], [%1], 16, %2;" \
                 :: "r"(dst), "l"(src), "r"(sz) : "memory")

// Fast, NaN-safe activations (budget 1e-3; these give ~1e-6).
__device__ __forceinline__ float fsigm(float x) {
    float e; asm("ex2.approx.f32 %0, %1;" : "=f"(e) : "f"(-1.4426950408889634f * x));
    float r; asm("rcp.approx.f32 %0, %1;" : "=f"(r) : "f"(1.0f + e));
    return r;
}
__device__ __forceinline__ float ftanh(float x) {
    float ax = fabsf(x);
    float e; asm("ex2.approx.f32 %0, %1;" : "=f"(e) : "f"(-2.885390081777927f * ax));
    float r; asm("rcp.approx.f32 %0, %1;" : "=f"(r) : "f"(1.0f + e));
    return copysignf((1.0f - e) * r, x);
}

// ---------------------------------------------------------------------------
// One-time weight transpose: Wg[k*H + j] -> g_Wpack[(g*H+j)*HX + k].
// Also resets the grid barrier.
// ---------------------------------------------------------------------------
__global__ void pack_weights(const float* __restrict__ Wf, const float* __restrict__ Wi,
                             const float* __restrict__ Wc, const float* __restrict__ Wo) {
    if (blockIdx.x == 0 && blockIdx.y == 0 && blockIdx.z == 0 &&
        threadIdx.x == 0 && threadIdx.y == 0) g_bar = 0u;
    __shared__ float tile[32][33];
    const int g  = blockIdx.z;
    const float* W = (g == 0) ? Wf : (g == 1) ? Wi : (g == 2) ? Wc : Wo;
    const int j0 = blockIdx.x * 32;
    const int k0 = blockIdx.y * 32;
    const int tx = threadIdx.x, ty0 = threadIdx.y;
    #pragma unroll
    for (int ty = ty0; ty < 32; ty += 8)
        tile[ty][tx] = W[(size_t)(k0 + ty) * HH + (j0 + tx)];
    __syncthreads();
    #pragma unroll
    for (int ty = ty0; ty < 32; ty += 8)
        g_Wpack[(size_t)(g * HH + j0 + ty) * HXX + (k0 + tx)] = tile[tx][ty];
}

// ---------------------------------------------------------------------------
// Stage iteration i via cp.async.cg. For kg, window k0 = kg*192 + i*32.
// Windows never straddle the h/x boundary (512 = 384 + 4*32).
// 4096 float4 total / 512 threads = 8 each. t==0 h-windows: zero-fill (sz=0).
// ---------------------------------------------------------------------------
__device__ __forceinline__ void stage(uint32_t vdst, const float* __restrict__ x,
                                      const float* __restrict__ out, int t, int i, int tid) {
    #pragma unroll
    for (int j = 0; j < 8; j++) {
        const int idx = tid + j * NTHR;        // 0..4095
        const int kgw = idx >> 10;             // 4 kg slices
        const int rem = idx & 1023;
        const int b   = rem >> 3;
        const int q   = rem & 7;
        const int k0  = kgw * KPG + i * KC;
        const uint32_t d = vdst + (uint32_t)(((kgw * BB + b) * VROW + q * 4) * 4);
        const float* s;
        int sz = 16;
        if (k0 < 512) {
            if (t == 0) { s = x; sz = 0; }     // zero-fill, dummy valid src
            else s = out + (size_t)(t - 1) * (BB * HH) + (size_t)b * HH + k0 + q * 4;
        } else {
            s = x + (size_t)t * (BB * II) + (size_t)b * II + (k0 - 512) + q * 4;
        }
        CP16(d, s, sz);
    }
}

// ---------------------------------------------------------------------------
// Persistent kernel. Thread map: kg = tid>>7; r = tid&127; tx = r&3 (H-col
// j0+tx across all 4 gates); ty = r>>2 (b = ty + 32*bi).
// ---------------------------------------------------------------------------
__global__ void __launch_bounds__(NTHR, 1)
lstm_persist(const float* __restrict__ x,
             const float* __restrict__ bf, const float* __restrict__ bi_,
             const float* __restrict__ bc, const float* __restrict__ bo,
             float* out)
{
    extern __shared__ float sm[];
    float* Ws  = sm;                 // [GCN][WROW]
    float* vsm = sm + WS_ELEMS;      // 2 x [KG][BB][VROW]
    const uint32_t vsm_s = (uint32_t)__cvta_generic_to_shared(vsm);

    const int tid = threadIdx.x;
    const int cid = blockIdx.x;
    const int j0  = cid * JPC;
    const int kg  = tid >> 7;
    const int r   = tid & 127;
    const int tx  = r & 3;
    const int ty  = r >> 2;

    // Stage this CTA's 16 weight columns once (49KB), coalesced.
    {
        const float4* wp = (const float4*)g_Wpack;
        #pragma unroll
        for (int it = 0; it < (GCN * (HXX / 4)) / NTHR; ++it) {   // 6 iters
            const int idx = tid + it * NTHR;
            const int gc  = idx / (HXX / 4);
            const int k4  = idx % (HXX / 4);
            const int g = gc >> 2, jj = gc & 3;
            *(float4*)(Ws + gc * WROW + k4 * 4) =
                wp[(size_t)(g * HH + j0 + jj) * (HXX / 4) + k4];
        }
    }

    // Bias per gate (col j0+tx of all 4 gates); added in kg==0 only.
    unsigned long long ub[4];
    #pragma unroll
    for (int gi = 0; gi < 4; gi++) {
        const float* bp = (gi == 0) ? bf : (gi == 1) ? bi_ : (gi == 2) ? bc : bo;
        ub[gi] = (kg == 0) ? (unsigned long long)__float_as_uint(bp[j0 + tx]) : 0ull;
    }
    __syncthreads();

    const float* wthr = Ws + tx * WROW + kg * KPG;   // +gi*4*WROW per gate

    for (int t = 0; t < TT; ++t) {
        unsigned long long acc[4][4];
        #pragma unroll
        for (int gi = 0; gi < 4; gi++)
            #pragma unroll
            for (int bi = 0; bi < 4; bi++) acc[gi][bi] = ub[gi];

        stage(vsm_s, x, out, t, 0, tid);
        asm volatile("cp.async.commit_group;");
        asm volatile("cp.async.wait_group 0;" ::: "memory");
        __syncthreads();

        #pragma unroll 1
        for (int i = 0; i < 6; ++i) {
            const int buf = i & 1;
            if (i < 5) {
                stage(vsm_s + (uint32_t)((buf ^ 1) * VS_ELEMS * 4), x, out, t, i + 1, tid);
                asm volatile("cp.async.commit_group;");
            }
            const float* wr = wthr + i * KC;
            const float* vb = vsm + buf * VS_ELEMS + (kg * BB + ty) * VROW;

            #pragma unroll
            for (int kk = 0; kk < KC; kk += 4) {
                ulonglong2 w[4], v[4];
                #pragma unroll
                for (int gi = 0; gi < 4; gi++)
                    w[gi] = *(const ulonglong2*)(wr + gi * (4 * WROW) + kk);
                #pragma unroll
                for (int bi = 0; bi < 4; bi++)
                    v[bi] = *(const ulonglong2*)(vb + bi * (32 * VROW) + kk);
                #pragma unroll
                for (int gi = 0; gi < 4; gi++)
                    #pragma unroll
                    for (int bi = 0; bi < 4; bi++) {
                        FMA2(acc[gi][bi], w[gi].x, v[bi].x);
                        FMA2(acc[gi][bi], w[gi].y, v[bi].y);
                    }
            }
            if (i < 5) {
                asm volatile("cp.async.wait_group 0;" ::: "memory");
                __syncthreads();
            }
        }

        // kg-partial exchange: gsm[kg][gc][b] (32KB) in buffer-0 region
        // (last compute iteration read buffer 1 — disjoint).
        float* gsm = vsm;
        #pragma unroll
        for (int gi = 0; gi < 4; gi++)
            #pragma unroll
            for (int bi = 0; bi < 4; bi++) {
                const unsigned long long a = acc[gi][bi];
                const float lo = __uint_as_float((unsigned)(a & 0xffffffffu));
                const float hi = __uint_as_float((unsigned)(a >> 32));
                gsm[((kg * GCN) + (gi * 4 + tx)) * BB + (ty + 32 * bi)] = lo + hi;
            }
        __syncthreads();

        // Elementwise update: 512 cells/CTA, 1 per thread; reduce 4 kg partials.
        {
            const int b = tid & 127, jj = tid >> 7;
            float gate[4];
            #pragma unroll
            for (int gi = 0; gi < 4; gi++) {
                float s = 0.f;
                #pragma unroll
                for (int k = 0; k < KG; k++)
                    s += gsm[(k * GCN + gi * 4 + jj) * BB + b];
                gate[gi] = s;
            }
            const float fs = fsigm(gate[0]);
            const float is = fsigm(gate[1]);
            const float os = fsigm(gate[3]);
            const float Cold = (t == 0) ? 0.0f : g_C[b * HH + j0 + jj];
            const float Cnew = fs * Cold + is * ftanh(gate[2]);
            g_C[b * HH + j0 + jj] = Cnew;
            out[(size_t)t * (BB * HH) + (size_t)b * HH + j0 + jj] = os * ftanh(Cnew);
        }

        // Grid barrier (release add / acquire poll). All 128 CTAs resident.
        if (t < TT - 1) {
            __syncthreads();
            if (tid == 0) {
                asm volatile("red.release.gpu.global.add.u32 [%0], %1;"
                             :: "l"(&g_bar), "r"(1u) : "memory");
                const unsigned target = (unsigned)NCTA * (unsigned)(t + 1);
                unsigned v;
                do {
                    asm volatile("ld.acquire.gpu.global.u32 %0, [%1];"
                                 : "=r"(v) : "l"(&g_bar) : "memory");
                } while (v < target);
            }
            __syncthreads();
        }
    }
}

// ---------------------------------------------------------------------------
extern "C" void kernel_launch(void* const* d_in, const int* in_sizes, int n_in,
                              void* d_out, int out_size) {
    (void)in_sizes; (void)n_in; (void)out_size;
    const float* x  = (const float*)d_in[0];
    const float* Wf = (const float*)d_in[1];
    const float* bf = (const float*)d_in[2];
    const float* Wi = (const float*)d_in[3];
    const float* bi = (const float*)d_in[4];
    const float* Wc = (const float*)d_in[5];
    const float* bc = (const float*)d_in[6];
    const float* Wo = (const float*)d_in[7];
    const float* bo = (const float*)d_in[8];
    float* out = (float*)d_out;

    cudaFuncSetAttribute(lstm_persist, cudaFuncAttributeMaxDynamicSharedMemorySize, SMEM_BYTES);

    pack_weights<<<dim3(HH / 32, HXX / 32, 4), dim3(32, 8)>>>(Wf, Wi, Wc, Wo);
    lstm_persist<<<NCTA, NTHR, SMEM_BYTES>>>(x, bf, bi, bc, bo, out);
}

// round 12
// speedup vs baseline: 1.3117x; 1.0012x over previous
#include <cuda_runtime.h>
#include <cstdint>

#define TT   512
#define BB   128
#define II   256
#define HH   512
#define HXX  768
#define NCTA 128      // one CTA per 4 H-columns; all co-resident (<=148 SMs)
#define JPC  4
#define GCN  16       // gate-cols per CTA (4 gates * 4 cols)
#define NTHR 512      // 4 k-groups x 128 threads
#define KG   4
#define KPG  192      // k per group
#define KC   32       // k window per iteration (6 iterations)
#define WROW 772      // padded weight row: tx*772 words -> banks {0,4,8,12}, conflict-free
#define VROW 36       // padded v row: ty*36 words -> full bank coverage, conflict-free
#define VS_ELEMS (KG * BB * VROW)       // 18432 floats per buffer
#define WS_ELEMS (GCN * WROW)           // 12352 floats
#define SMEM_BYTES ((WS_ELEMS + 2 * VS_ELEMS) * 4)   // 196864 B

__device__ float    g_C[BB * HH];
__device__ float    g_Wpack[4 * HH * HXX];   // [g][j][k], k contiguous
__device__ unsigned g_bar;

// f32x2 packed FMA (FFMA2): 2 MACs/instr.
#define FMA2(acc, a, b) \
    asm("fma.rn.f32x2 %0, %1, %2, %0;" : "+l"(acc) : "l"(a), "l"(b))

// 16B async copy, L2-direct (.cg). sz=0 -> zero-fill destination.
#define CP16(dst, src, sz) \
    asm volatile("cp.async.cg.shared.global [%0], [%1], 16, %2;" \
                 :: "r"(dst), "l"(src), "r"(sz) : "memory")

// Fast, NaN-safe activations (budget 1e-3; these give ~1e-6).
__device__ __forceinline__ float fsigm(float x) {
    float e; asm("ex2.approx.f32 %0, %1;" : "=f"(e) : "f"(-1.4426950408889634f * x));
    float r; asm("rcp.approx.f32 %0, %1;" : "=f"(r) : "f"(1.0f + e));
    return r;
}
__device__ __forceinline__ float ftanh(float x) {
    float ax = fabsf(x);
    float e; asm("ex2.approx.f32 %0, %1;" : "=f"(e) : "f"(-2.885390081777927f * ax));
    float r; asm("rcp.approx.f32 %0, %1;" : "=f"(r) : "f"(1.0f + e));
    return copysignf((1.0f - e) * r, x);
}

// ---------------------------------------------------------------------------
// One-time weight transpose: Wg[k*H + j] -> g_Wpack[(g*H+j)*HX + k].
// Also resets the grid barrier.
// ---------------------------------------------------------------------------
__global__ void pack_weights(const float* __restrict__ Wf, const float* __restrict__ Wi,
                             const float* __restrict__ Wc, const float* __restrict__ Wo) {
    if (blockIdx.x == 0 && blockIdx.y == 0 && blockIdx.z == 0 &&
        threadIdx.x == 0 && threadIdx.y == 0) g_bar = 0u;
    __shared__ float tile[32][33];
    const int g  = blockIdx.z;
    const float* W = (g == 0) ? Wf : (g == 1) ? Wi : (g == 2) ? Wc : Wo;
    const int j0 = blockIdx.x * 32;
    const int k0 = blockIdx.y * 32;
    const int tx = threadIdx.x, ty0 = threadIdx.y;
    #pragma unroll
    for (int ty = ty0; ty < 32; ty += 8)
        tile[ty][tx] = W[(size_t)(k0 + ty) * HH + (j0 + tx)];
    __syncthreads();
    #pragma unroll
    for (int ty = ty0; ty < 32; ty += 8)
        g_Wpack[(size_t)(g * HH + j0 + ty) * HXX + (k0 + tx)] = tile[tx][ty];
}

// ---------------------------------------------------------------------------
// Stage iteration i via cp.async.cg. For kg, window k0 = kg*192 + i*32.
// Windows never straddle the h/x boundary (512 = 384 + 4*32).
// 4096 float4 total / 512 threads = 8 each. t==0 h-windows: zero-fill (sz=0).
// ---------------------------------------------------------------------------
__device__ __forceinline__ void stage(uint32_t vdst, const float* __restrict__ x,
                                      const float* __restrict__ out, int t, int i, int tid) {
    #pragma unroll
    for (int j = 0; j < 8; j++) {
        const int idx = tid + j * NTHR;        // 0..4095
        const int kgw = idx >> 10;             // 4 kg slices
        const int rem = idx & 1023;
        const int b   = rem >> 3;
        const int q   = rem & 7;
        const int k0  = kgw * KPG + i * KC;
        const uint32_t d = vdst + (uint32_t)(((kgw * BB + b) * VROW + q * 4) * 4);
        const float* s;
        int sz = 16;
        if (k0 < 512) {
            if (t == 0) { s = x; sz = 0; }     // zero-fill, dummy valid src
            else s = out + (size_t)(t - 1) * (BB * HH) + (size_t)b * HH + k0 + q * 4;
        } else {
            s = x + (size_t)t * (BB * II) + (size_t)b * II + (k0 - 512) + q * 4;
        }
        CP16(d, s, sz);
    }
}

// ---------------------------------------------------------------------------
// Persistent kernel. Thread map: kg = tid>>7; r = tid&127; tx = r&3 (H-col
// j0+tx across all 4 gates); ty = r>>2 (b = ty + 32*bi).
// ---------------------------------------------------------------------------
__global__ void __launch_bounds__(NTHR, 1)
lstm_persist(const float* __restrict__ x,
             const float* __restrict__ bf, const float* __restrict__ bi_,
             const float* __restrict__ bc, const float* __restrict__ bo,
             float* out)
{
    extern __shared__ float sm[];
    float* Ws  = sm;                 // [GCN][WROW]
    float* vsm = sm + WS_ELEMS;      // 2 x [KG][BB][VROW]
    const uint32_t vsm_s = (uint32_t)__cvta_generic_to_shared(vsm);

    const int tid = threadIdx.x;
    const int cid = blockIdx.x;
    const int j0  = cid * JPC;
    const int kg  = tid >> 7;
    const int r   = tid & 127;
    const int tx  = r & 3;
    const int ty  = r >> 2;

    // Stage this CTA's 16 weight columns once (49KB), coalesced.
    {
        const float4* wp = (const float4*)g_Wpack;
        #pragma unroll
        for (int it = 0; it < (GCN * (HXX / 4)) / NTHR; ++it) {   // 6 iters
            const int idx = tid + it * NTHR;
            const int gc  = idx / (HXX / 4);
            const int k4  = idx % (HXX / 4);
            const int g = gc >> 2, jj = gc & 3;
            *(float4*)(Ws + gc * WROW + k4 * 4) =
                wp[(size_t)(g * HH + j0 + jj) * (HXX / 4) + k4];
        }
    }

    // Bias per gate (col j0+tx of all 4 gates); added in kg==0 only.
    unsigned long long ub[4];
    #pragma unroll
    for (int gi = 0; gi < 4; gi++) {
        const float* bp = (gi == 0) ? bf : (gi == 1) ? bi_ : (gi == 2) ? bc : bo;
        ub[gi] = (kg == 0) ? (unsigned long long)__float_as_uint(bp[j0 + tx]) : 0ull;
    }
    __syncthreads();

    const float* wthr = Ws + tx * WROW + kg * KPG;   // +gi*4*WROW per gate

    for (int t = 0; t < TT; ++t) {
        unsigned long long acc[4][4];
        #pragma unroll
        for (int gi = 0; gi < 4; gi++)
            #pragma unroll
            for (int bi = 0; bi < 4; bi++) acc[gi][bi] = ub[gi];

        stage(vsm_s, x, out, t, 0, tid);
        asm volatile("cp.async.commit_group;");
        asm volatile("cp.async.wait_group 0;" ::: "memory");
        __syncthreads();

        #pragma unroll 1
        for (int i = 0; i < 6; ++i) {
            const int buf = i & 1;
            if (i < 5) {
                stage(vsm_s + (uint32_t)((buf ^ 1) * VS_ELEMS * 4), x, out, t, i + 1, tid);
                asm volatile("cp.async.commit_group;");
            }
            const float* wr = wthr + i * KC;
            const float* vb = vsm + buf * VS_ELEMS + (kg * BB + ty) * VROW;

            #pragma unroll
            for (int kk = 0; kk < KC; kk += 4) {
                ulonglong2 w[4], v[4];
                #pragma unroll
                for (int gi = 0; gi < 4; gi++)
                    w[gi] = *(const ulonglong2*)(wr + gi * (4 * WROW) + kk);
                #pragma unroll
                for (int bi = 0; bi < 4; bi++)
                    v[bi] = *(const ulonglong2*)(vb + bi * (32 * VROW) + kk);
                #pragma unroll
                for (int gi = 0; gi < 4; gi++)
                    #pragma unroll
                    for (int bi = 0; bi < 4; bi++) {
                        FMA2(acc[gi][bi], w[gi].x, v[bi].x);
                        FMA2(acc[gi][bi], w[gi].y, v[bi].y);
                    }
            }
            if (i < 5) {
                asm volatile("cp.async.wait_group 0;" ::: "memory");
                __syncthreads();
            }
        }

        // kg-partial exchange: gsm[kg][gc][b] (32KB) in buffer-0 region
        // (last compute iteration read buffer 1 — disjoint).
        float* gsm = vsm;
        #pragma unroll
        for (int gi = 0; gi < 4; gi++)
            #pragma unroll
            for (int bi = 0; bi < 4; bi++) {
                const unsigned long long a = acc[gi][bi];
                const float lo = __uint_as_float((unsigned)(a & 0xffffffffu));
                const float hi = __uint_as_float((unsigned)(a >> 32));
                gsm[((kg * GCN) + (gi * 4 + tx)) * BB + (ty + 32 * bi)] = lo + hi;
            }
        __syncthreads();

        // Elementwise update: 512 cells/CTA, 1 per thread; reduce 4 kg partials.
        {
            const int b = tid & 127, jj = tid >> 7;
            float gate[4];
            #pragma unroll
            for (int gi = 0; gi < 4; gi++) {
                float s = 0.f;
                #pragma unroll
                for (int k = 0; k < KG; k++)
                    s += gsm[(k * GCN + gi * 4 + jj) * BB + b];
                gate[gi] = s;
            }
            const float fs = fsigm(gate[0]);
            const float is = fsigm(gate[1]);
            const float os = fsigm(gate[3]);
            const float Cold = (t == 0) ? 0.0f : g_C[b * HH + j0 + jj];
            const float Cnew = fs * Cold + is * ftanh(gate[2]);
            g_C[b * HH + j0 + jj] = Cnew;
            out[(size_t)t * (BB * HH) + (size_t)b * HH + j0 + jj] = os * ftanh(Cnew);
        }

        // Grid barrier (release add / acquire poll). All 128 CTAs resident.
        if (t < TT - 1) {
            __syncthreads();
            if (tid == 0) {
                asm volatile("red.release.gpu.global.add.u32 [%0], %1;"
                             :: "l"(&g_bar), "r"(1u) : "memory");
                const unsigned target = (unsigned)NCTA * (unsigned)(t + 1);
                unsigned v;
                do {
                    asm volatile("ld.acquire.gpu.global.u32 %0, [%1];"
                                 : "=r"(v) : "l"(&g_bar) : "memory");
                } while (v < target);
            }
            __syncthreads();
        }
    }
}

// ---------------------------------------------------------------------------
extern "C" void kernel_launch(void* const* d_in, const int* in_sizes, int n_in,
                              void* d_out, int out_size) {
    (void)in_sizes; (void)n_in; (void)out_size;
    const float* x  = (const float*)d_in[0];
    const float* Wf = (const float*)d_in[1];
    const float* bf = (const float*)d_in[2];
    const float* Wi = (const float*)d_in[3];
    const float* bi = (const float*)d_in[4];
    const float* Wc = (const float*)d_in[5];
    const float* bc = (const float*)d_in[6];
    const float* Wo = (const float*)d_in[7];
    const float* bo = (const float*)d_in[8];
    float* out = (float*)d_out;

    cudaFuncSetAttribute(lstm_persist, cudaFuncAttributeMaxDynamicSharedMemorySize, SMEM_BYTES);

    pack_weights<<<dim3(HH / 32, HXX / 32, 4), dim3(32, 8)>>>(Wf, Wi, Wc, Wo);
    lstm_persist<<<NCTA, NTHR, SMEM_BYTES>>>(x, bf, bi, bc, bo, out);
}

// round 14
// speedup vs baseline: 1.7587x; 1.3407x over previous
#include <cuda_runtime.h>
#include <cuda_bf16.h>
#include <mma.h>
#include <cstdint>
using namespace nvcuda;

#define TT 512
#define BB 128
#define II 256
#define HH 512
#define NCTA 128
#define NTHR 256

#define WLD 776                        // W smem row pitch (768+8): 1552B %128 = 16 -> conflict-free
#define VLD 72                         // v smem row pitch (64+8):  144B  %128 = 16 -> conflict-free
#define GLD 132                        // gate smem row pitch (fp32)
#define SM_BIAS 0
#define SM_W    128
#define WBYTES  (2*16*WLD*2)           // 49664: [hl][16 gc][776] bf16
#define SM_V0   (SM_W + WBYTES)        // 49792 (128-aligned)
#define VBUF_B  (2*2*128*VLD*2)        // 73728: [kh][hl][128 b][72] bf16
#define VBUF_E  (VBUF_B/2)             // elems
#define SMEM_BYTES (SM_V0 + 2*VBUF_B)  // 197248 < 227KB

// Device scratch (static — no allocations).
__device__ __align__(16) __nv_bfloat16 g_Wsplit[(size_t)NCTA * 2 * 16 * 768];     // 12.6MB
__device__ __align__(16) __nv_bfloat16 g_xsplit[(size_t)TT * 2 * BB * II];        // 67MB
__device__ __align__(16) __nv_bfloat16 g_hsplit[2 * 2 * BB * HH];                 // 512KB
__device__ unsigned g_bar;

#define CP16(dst, src, sz) \
    asm volatile("cp.async.cg.shared.global [%0], [%1], 16, %2;" \
                 :: "r"(dst), "l"(src), "r"(sz) : "memory")

__device__ __forceinline__ float fsigm(float x) {
    float e; asm("ex2.approx.f32 %0, %1;" : "=f"(e) : "f"(-1.4426950408889634f * x));
    float r; asm("rcp.approx.f32 %0, %1;" : "=f"(r) : "f"(1.0f + e));
    return r;
}
__device__ __forceinline__ float ftanh(float x) {
    float ax = fabsf(x);
    float e; asm("ex2.approx.f32 %0, %1;" : "=f"(e) : "f"(-2.885390081777927f * ax));
    float r; asm("rcp.approx.f32 %0, %1;" : "=f"(r) : "f"(1.0f + e));
    return copysignf((1.0f - e) * r, x);
}

// ---------------------------------------------------------------------------
// pack_W: per-CTA A tiles. Row gc = g*4+jj, A[gc][k] = W_g[k][cta*4+jj],
// split into bf16 hi/lo planes. Also resets the grid barrier.
// ---------------------------------------------------------------------------
__global__ void pack_W(const float* __restrict__ Wf, const float* __restrict__ Wi,
                       const float* __restrict__ Wc, const float* __restrict__ Wo) {
    if (blockIdx.x == 0 && blockIdx.y == 0 && threadIdx.x == 0) g_bar = 0u;
    const int cta = blockIdx.x, g = blockIdx.y;
    const float* W = (g == 0) ? Wf : (g == 1) ? Wi : (g == 2) ? Wc : Wo;
    __nv_bfloat16* base = g_Wsplit + (size_t)cta * (2 * 16 * 768);
    for (int l = 0; l < 12; ++l) {
        const int idx = threadIdx.x + l * 256;     // 0..3071
        const int jj = idx / 768, k = idx % 768;
        const float w = W[(size_t)k * HH + cta * 4 + jj];
        const __nv_bfloat16 hi = __float2bfloat16(w);
        const __nv_bfloat16 lo = __float2bfloat16(w - __bfloat162float(hi));
        base[(0 * 16 + g * 4 + jj) * 768 + k] = hi;
        base[(1 * 16 + g * 4 + jj) * 768 + k] = lo;
    }
}

// pack_x: [t][hl][b][256] split-bf16, fully coalesced.
__global__ void pack_x(const float* __restrict__ x) {
    const int t = blockIdx.x;
    const float* xt = x + (size_t)t * (BB * II);
    __nv_bfloat16* dh = g_xsplit + ((size_t)t * 2 + 0) * (BB * II);
    __nv_bfloat16* dl = g_xsplit + ((size_t)t * 2 + 1) * (BB * II);
    for (int l = 0; l < (BB * II) / 256; ++l) {
        const int idx = threadIdx.x + l * 256;
        const float v = xt[idx];
        const __nv_bfloat16 hi = __float2bfloat16(v);
        dh[idx] = hi;
        dl[idx] = __float2bfloat16(v - __bfloat162float(hi));
    }
}

// ---------------------------------------------------------------------------
// Stage chunk-iter i: for kh in {0,1}, hl in {0,1}: 64-k window at
// k0 = kh*384 + i*64 for all 128 batches. h region (k<512) from g_hsplit
// (zero-filled at t=0), else x from g_xsplit. 4096 x 16B, 16 per thread.
// ---------------------------------------------------------------------------
__device__ __forceinline__ void stage(uint32_t vdst, int t, int i, int tid) {
    const int par = (t & 1) ^ 1;
    #pragma unroll
    for (int j = 0; j < 16; ++j) {
        const int idx = tid + j * NTHR;            // 0..4095
        const int seg = idx & 7;
        const int b   = (idx >> 3) & 127;
        const int hl  = (idx >> 10) & 1;
        const int kh  = idx >> 11;
        const int k0  = kh ? 384 + i * 64 : i * 64;
        const uint32_t d = vdst + (uint32_t)((((kh * 2 + hl) * 128 + b) * VLD * 2) + seg * 16);
        if (k0 < 512) {
            const char* s = (const char*)g_hsplit
                + ((size_t)((par * 2 + hl) * 128 + b) * HH + k0) * 2 + seg * 16;
            CP16(d, s, (t == 0) ? 0 : 16);
        } else {
            const char* s = (const char*)g_xsplit
                + (((size_t)t * 2 + hl) * (BB * II) + (size_t)b * II + (k0 - 512)) * 2 + seg * 16;
            CP16(d, s, 16);
        }
    }
}

// ---------------------------------------------------------------------------
// Persistent wmma kernel. 8 warps: kh = warp>>2 (K-half), nw = warp&3 (n32).
// Per step: acc[2] m16n16 tiles over 6 chunk-iters x 4 k-tiles x 3 split terms.
// ---------------------------------------------------------------------------
__global__ void __launch_bounds__(NTHR, 1)
lstm_wmma(const float* __restrict__ bf, const float* __restrict__ bi_,
          const float* __restrict__ bc, const float* __restrict__ bo,
          float* __restrict__ out)
{
    extern __shared__ char smc[];
    float* bias = (float*)(smc + SM_BIAS);
    __nv_bfloat16* Wsm = (__nv_bfloat16*)(smc + SM_W);
    __nv_bfloat16* vsm = (__nv_bfloat16*)(smc + SM_V0);
    float* gsm = (float*)(smc + SM_V0);        // aliases v-buffer 0 (safe: see below)
    const uint32_t vsm_s = (uint32_t)__cvta_generic_to_shared(vsm);

    const int tid  = threadIdx.x;
    const int cta  = blockIdx.x;
    const int j0   = cta * 4;
    const int warp = tid >> 5, lane = tid & 31;
    const int kh   = warp >> 2, nw = warp & 3;

    // Load W tile (hi+lo) into smem once, 16B chunks.
    {
        const uint4* src = (const uint4*)(g_Wsplit + (size_t)cta * (2 * 16 * 768));
        for (int rr = warp; rr < 32; rr += 8) {
            const int hl = rr >> 4, gc = rr & 15;
            uint4* drow = (uint4*)(Wsm + hl * (16 * WLD) + gc * WLD);
            const uint4* srow = src + rr * 96;
            #pragma unroll
            for (int u = lane; u < 96; u += 32) drow[u] = srow[u];
        }
    }
    if (tid < 16) {
        const int g = tid >> 2;
        const float* bp = (g == 0) ? bf : (g == 1) ? bi_ : (g == 2) ? bc : bo;
        bias[tid] = bp[j0 + (tid & 3)];
    }
    __syncthreads();

    float Creg[2] = {0.f, 0.f};

    wmma::fragment<wmma::matrix_a, 16, 16, 16, __nv_bfloat16, wmma::row_major> fah, fal;
    wmma::fragment<wmma::matrix_b, 16, 16, 16, __nv_bfloat16, wmma::col_major> fb;
    wmma::fragment<wmma::accumulator, 16, 16, 16, float> acc[2];

    for (int t = 0; t < TT; ++t) {
        wmma::fill_fragment(acc[0], 0.0f);
        wmma::fill_fragment(acc[1], 0.0f);

        stage(vsm_s, t, 0, tid);
        asm volatile("cp.async.commit_group;");
        asm volatile("cp.async.wait_group 0;" ::: "memory");
        __syncthreads();

        #pragma unroll 1
        for (int i = 0; i < 6; ++i) {
            const int buf = i & 1;
            if (i < 5) {
                stage(vsm_s + (uint32_t)((buf ^ 1) * VBUF_B), t, i + 1, tid);
                asm volatile("cp.async.commit_group;");
            }
            const __nv_bfloat16* vb = vsm + buf * VBUF_E;
            #pragma unroll
            for (int kt = 0; kt < 4; ++kt) {
                const int kg = kh * 384 + i * 64 + kt * 16;
                wmma::load_matrix_sync(fah, Wsm + kg, WLD);
                wmma::load_matrix_sync(fal, Wsm + 16 * WLD + kg, WLD);
                #pragma unroll
                for (int nt = 0; nt < 2; ++nt) {
                    const int n0 = nw * 32 + nt * 16;
                    const __nv_bfloat16* bh = vb + ((kh * 2 + 0) * 128 + n0) * VLD + kt * 16;
                    const __nv_bfloat16* bl = vb + ((kh * 2 + 1) * 128 + n0) * VLD + kt * 16;
                    wmma::load_matrix_sync(fb, bh, VLD);
                    wmma::mma_sync(acc[nt], fah, fb, acc[nt]);
                    wmma::mma_sync(acc[nt], fal, fb, acc[nt]);
                    wmma::load_matrix_sync(fb, bl, VLD);
                    wmma::mma_sync(acc[nt], fah, fb, acc[nt]);
                }
            }
            if (i < 5) {
                asm volatile("cp.async.wait_group 0;" ::: "memory");
                __syncthreads();
            }
        }

        // Partial store: gsm[kh][m 16][GLD] in buffer-0 region (i=5 read buffer 1;
        // all warps passed the i=4 end-sync, so buffer 0 is no longer being read).
        #pragma unroll
        for (int nt = 0; nt < 2; ++nt)
            wmma::store_matrix_sync(gsm + kh * (16 * GLD) + nw * 32 + nt * 16,
                                    acc[nt], GLD, wmma::mem_row_major);
        __syncthreads();

        // Cell update: 512 cells, 2/thread; C in registers; h -> out + split-bf16.
        const int par = t & 1;
        #pragma unroll
        for (int e = 0; e < 2; ++e) {
            const int cell = tid + e * NTHR;
            const int b = cell & 127, jj = cell >> 7;
            float gate[4];
            #pragma unroll
            for (int g = 0; g < 4; ++g)
                gate[g] = gsm[(g * 4 + jj) * GLD + b]
                        + gsm[16 * GLD + (g * 4 + jj) * GLD + b]
                        + bias[g * 4 + jj];
            const float Cnew = fsigm(gate[0]) * Creg[e] + fsigm(gate[1]) * ftanh(gate[2]);
            Creg[e] = Cnew;
            const float h = fsigm(gate[3]) * ftanh(Cnew);
            out[(size_t)t * (BB * HH) + (size_t)b * HH + j0 + jj] = h;
            const __nv_bfloat16 hi = __float2bfloat16(h);
            const __nv_bfloat16 lo = __float2bfloat16(h - __bfloat162float(hi));
            g_hsplit[(size_t)((par * 2 + 0) * 128 + b) * HH + j0 + jj] = hi;
            g_hsplit[(size_t)((par * 2 + 1) * 128 + b) * HH + j0 + jj] = lo;
        }

        // Grid barrier (release add / acquire poll); 128 CTAs all resident.
        if (t < TT - 1) {
            __syncthreads();
            if (tid == 0) {
                asm volatile("red.release.gpu.global.add.u32 [%0], %1;"
                             :: "l"(&g_bar), "r"(1u) : "memory");
                const unsigned target = (unsigned)NCTA * (unsigned)(t + 1);
                unsigned v;
                do {
                    asm volatile("ld.acquire.gpu.global.u32 %0, [%1];"
                                 : "=r"(v) : "l"(&g_bar) : "memory");
                } while (v < target);
            }
            __syncthreads();
        }
    }
}

// ---------------------------------------------------------------------------
extern "C" void kernel_launch(void* const* d_in, const int* in_sizes, int n_in,
                              void* d_out, int out_size) {
    (void)in_sizes; (void)n_in; (void)out_size;
    const float* x  = (const float*)d_in[0];
    const float* Wf = (const float*)d_in[1];
    const float* bf = (const float*)d_in[2];
    const float* Wi = (const float*)d_in[3];
    const float* bi = (const float*)d_in[4];
    const float* Wc = (const float*)d_in[5];
    const float* bc = (const float*)d_in[6];
    const float* Wo = (const float*)d_in[7];
    const float* bo = (const float*)d_in[8];
    float* out = (float*)d_out;

    cudaFuncSetAttribute(lstm_wmma, cudaFuncAttributeMaxDynamicSharedMemorySize, SMEM_BYTES);

    // Exactly 3 launches per call (ncu -s5 lands on lstm_wmma in replay 2).
    pack_W<<<dim3(NCTA, 4), 256>>>(Wf, Wi, Wc, Wo);    // also resets g_bar
    pack_x<<<TT, 256>>>(x);
    lstm_wmma<<<NCTA, NTHR, SMEM_BYTES>>>(bf, bi, bc, bo, out);
}

// round 15
// speedup vs baseline: 2.1837x; 1.2416x over previous
#include <cuda_runtime.h>
#include <cuda_bf16.h>
#include <mma.h>
#include <cstdint>
using namespace nvcuda;

#define TT 512
#define BB 128
#define II 256
#define HH 512
#define NCTA 128      // 64 H-tiles x 2 batch-halves; all co-resident
#define NTHR 256

#define WLD 776                         // 1552B row %128 = 16 -> conflict-free
#define VLD 72                          // 144B row  %128 = 16 -> conflict-free
#define GLD 68
#define SM_BIAS 0                       // 32 floats
#define SM_W    128
#define WBYTES  (2*32*WLD*2)            // 99328: [hl][32 rows][776] bf16
#define SM_V0   (SM_W + WBYTES)         // 99456
#define VBUF_B  (2*2*64*VLD*2)          // 36864: [half][hl][64 b][72] bf16
#define VBUF_E  (VBUF_B/2)
#define SM_GSM  (SM_V0 + 2*VBUF_B)      // 173184: [kh 2][32 m][GLD] fp32
#define SMEM_BYTES (SM_GSM + 2*32*GLD*4)  // 190592 < 227KB

// Device scratch (static — no allocations).
__device__ __align__(16) __nv_bfloat16 g_Wsplit[64ULL * 2 * 32 * 768];        // 6.3MB
__device__ __align__(16) __nv_bfloat16 g_xsplit[(size_t)TT * 2 * BB * II];    // 67MB
__device__ __align__(16) __nv_bfloat16 g_hsplit[2 * 2 * BB * HH];             // 512KB
__device__ unsigned g_bar;

#define CP16(dst, src, sz) \
    asm volatile("cp.async.cg.shared.global [%0], [%1], 16, %2;" \
                 :: "r"(dst), "l"(src), "r"(sz) : "memory")

// Chunk c -> two 64-k windows. Chunks 0,1 are pure-x (prefetchable across the
// grid barrier); chunks 2..5 carry the h-dependent windows.
__device__ __forceinline__ int win0(int c) { return (c < 2) ? 8 + c : c - 2; }   // kh=0
__device__ __forceinline__ int win1(int c) { return (c < 2) ? 10 + c : c + 2; }  // kh=1

__device__ __forceinline__ float fsigm(float x) {
    float e; asm("ex2.approx.f32 %0, %1;" : "=f"(e) : "f"(-1.4426950408889634f * x));
    float r; asm("rcp.approx.f32 %0, %1;" : "=f"(r) : "f"(1.0f + e));
    return r;
}
__device__ __forceinline__ float ftanh(float x) {
    float ax = fabsf(x);
    float e; asm("ex2.approx.f32 %0, %1;" : "=f"(e) : "f"(-2.885390081777927f * ax));
    float r; asm("rcp.approx.f32 %0, %1;" : "=f"(r) : "f"(1.0f + e));
    return copysignf((1.0f - e) * r, x);
}

// ---------------------------------------------------------------------------
// pack_W: per-H-tile A slices. Row r = g*8+jj, A[r][k] = W_g[k][hh*8+jj],
// split bf16 hi/lo planes. Resets the grid barrier.
// ---------------------------------------------------------------------------
__global__ void pack_W(const float* __restrict__ Wf, const float* __restrict__ Wi,
                       const float* __restrict__ Wc, const float* __restrict__ Wo) {
    if (blockIdx.x == 0 && blockIdx.y == 0 && threadIdx.x == 0) g_bar = 0u;
    const int hh = blockIdx.x, g = blockIdx.y;
    const float* W = (g == 0) ? Wf : (g == 1) ? Wi : (g == 2) ? Wc : Wo;
    __nv_bfloat16* base = g_Wsplit + (size_t)hh * (2 * 32 * 768);
    #pragma unroll
    for (int l = 0; l < 24; ++l) {
        const int idx = threadIdx.x + l * 256;     // 0..6143
        const int jj = idx / 768, k = idx % 768;
        const float w = W[(size_t)k * HH + hh * 8 + jj];
        const __nv_bfloat16 hi = __float2bfloat16(w);
        const __nv_bfloat16 lo = __float2bfloat16(w - __bfloat162float(hi));
        base[(0 * 32 + g * 8 + jj) * 768 + k] = hi;
        base[(1 * 32 + g * 8 + jj) * 768 + k] = lo;
    }
}

// pack_x: [t][hl][b][256] split-bf16, fully coalesced.
__global__ void pack_x(const float* __restrict__ x) {
    const int t = blockIdx.x;
    const float* xt = x + (size_t)t * (BB * II);
    __nv_bfloat16* dh = g_xsplit + ((size_t)t * 2 + 0) * (BB * II);
    __nv_bfloat16* dl = g_xsplit + ((size_t)t * 2 + 1) * (BB * II);
    #pragma unroll
    for (int l = 0; l < (BB * II) / 256; ++l) {
        const int idx = threadIdx.x + l * 256;
        const float v = xt[idx];
        const __nv_bfloat16 hi = __float2bfloat16(v);
        dh[idx] = hi;
        dl[idx] = __float2bfloat16(v - __bfloat162float(hi));
    }
}

// ---------------------------------------------------------------------------
// Stage chunk c for step t: both windows, both hl planes, 64 local batches.
// 2048 x 16B -> 8 per thread. h windows (k<512) zero-fill at t==0.
// ---------------------------------------------------------------------------
__device__ __forceinline__ void stage(uint32_t vdst, int t, int c, int tid, int nbase) {
    const int par = (t & 1) ^ 1;
    #pragma unroll
    for (int j = 0; j < 8; ++j) {
        const int idx = tid + j * NTHR;            // 0..2047
        const int seg  = idx & 7;
        const int b    = (idx >> 3) & 63;
        const int hl   = (idx >> 9) & 1;
        const int half = idx >> 10;
        const int w    = half ? win1(c) : win0(c);
        const int k0   = w * 64;
        const uint32_t d = vdst + (uint32_t)((((half * 2 + hl) * 64 + b) * VLD * 2) + seg * 16);
        if (k0 < 512) {
            const char* s = (const char*)g_hsplit
                + ((size_t)((par * 2 + hl) * 128 + nbase + b) * HH + k0 + seg * 8) * 2;
            CP16(d, s, (t == 0) ? 0 : 16);
        } else {
            const char* s = (const char*)g_xsplit
                + (((size_t)t * 2 + hl) * (BB * II) + (size_t)(nbase + b) * II
                   + (k0 - 512) + seg * 8) * 2;
            CP16(d, s, 16);
        }
    }
}

// ---------------------------------------------------------------------------
// Persistent wmma kernel. 8 warps: kh = warp>>2 (window of the chunk pair),
// nw = warp&3 (n16 of 64). mh (2 m16 tiles) unrolled inside.
// ---------------------------------------------------------------------------
__global__ void __launch_bounds__(NTHR, 1)
lstm_wmma(const float* __restrict__ bf, const float* __restrict__ bi_,
          const float* __restrict__ bc, const float* __restrict__ bo,
          float* __restrict__ out)
{
    extern __shared__ char smc[];
    float* bias = (float*)(smc + SM_BIAS);
    __nv_bfloat16* Wsm = (__nv_bfloat16*)(smc + SM_W);
    __nv_bfloat16* vsm = (__nv_bfloat16*)(smc + SM_V0);
    float* gsm = (float*)(smc + SM_GSM);
    const uint32_t vsm_s = (uint32_t)__cvta_generic_to_shared(vsm);

    const int tid  = threadIdx.x;
    const int hh   = blockIdx.x >> 1;              // H-tile (8 cols)
    const int nb   = blockIdx.x & 1;               // batch half
    const int nbase = nb * 64;
    const int j0   = hh * 8;
    const int warp = tid >> 5, lane = tid & 31;
    const int kh   = warp >> 2, nw = warp & 3;

    // W slice (hi+lo, 64 rows x 768) -> smem rows with pitch WLD.
    {
        const uint4* src = (const uint4*)(g_Wsplit + (size_t)hh * (2 * 32 * 768));
        for (int rr = warp; rr < 64; rr += 8) {
            uint4* drow = (uint4*)(Wsm + rr * WLD);
            const uint4* srow = src + rr * 96;
            #pragma unroll
            for (int u = lane; u < 96; u += 32) drow[u] = srow[u];
        }
    }
    if (tid < 32) {
        const int g = tid >> 3;
        const float* bp = (g == 0) ? bf : (g == 1) ? bi_ : (g == 2) ? bc : bo;
        bias[tid] = bp[j0 + (tid & 7)];
    }
    __syncthreads();

    float Creg[2] = {0.f, 0.f};

    wmma::fragment<wmma::matrix_a, 16, 16, 16, __nv_bfloat16, wmma::row_major> fah[2], fal[2];
    wmma::fragment<wmma::matrix_b, 16, 16, 16, __nv_bfloat16, wmma::col_major> fb;
    wmma::fragment<wmma::accumulator, 16, 16, 16, float> acc[2];

    // Prefetch chunk 0 (pure x) of t=0.
    stage(vsm_s, 0, 0, tid, nbase);
    asm volatile("cp.async.commit_group;");

    for (int t = 0; t < TT; ++t) {
        wmma::fill_fragment(acc[0], 0.0f);
        wmma::fill_fragment(acc[1], 0.0f);

        asm volatile("cp.async.wait_group 0;" ::: "memory");   // chunk 0 ready
        __syncthreads();

        #pragma unroll 1
        for (int i = 0; i < 6; ++i) {
            const int buf = i & 1;
            if (i < 5) {
                stage(vsm_s + (uint32_t)((buf ^ 1) * VBUF_B), t, i + 1, tid, nbase);
                asm volatile("cp.async.commit_group;");
            }
            const __nv_bfloat16* vb = vsm + buf * VBUF_E;
            const int w = kh ? win1(i) : win0(i);
            #pragma unroll
            for (int kt = 0; kt < 4; ++kt) {
                const int kg = w * 64 + kt * 16;
                #pragma unroll
                for (int mh = 0; mh < 2; ++mh) {
                    wmma::load_matrix_sync(fah[mh], Wsm + mh * (16 * WLD) + kg, WLD);
                    wmma::load_matrix_sync(fal[mh], Wsm + (32 + mh * 16) * WLD + kg, WLD);
                }
                const __nv_bfloat16* bh = vb + ((kh * 2 + 0) * 64 + nw * 16) * VLD + kt * 16;
                const __nv_bfloat16* bl = vb + ((kh * 2 + 1) * 64 + nw * 16) * VLD + kt * 16;
                wmma::load_matrix_sync(fb, bh, VLD);
                wmma::mma_sync(acc[0], fah[0], fb, acc[0]);
                wmma::mma_sync(acc[1], fah[1], fb, acc[1]);
                wmma::mma_sync(acc[0], fal[0], fb, acc[0]);
                wmma::mma_sync(acc[1], fal[1], fb, acc[1]);
                wmma::load_matrix_sync(fb, bl, VLD);
                wmma::mma_sync(acc[0], fah[0], fb, acc[0]);
                wmma::mma_sync(acc[1], fah[1], fb, acc[1]);
            }
            if (i < 5) {
                asm volatile("cp.async.wait_group 0;" ::: "memory");
                __syncthreads();
            }
        }

        // Partial store per kh, then combine.
        #pragma unroll
        for (int mh = 0; mh < 2; ++mh)
            wmma::store_matrix_sync(gsm + kh * (32 * GLD) + (mh * 16) * GLD + nw * 16,
                                    acc[mh], GLD, wmma::mem_row_major);
        __syncthreads();

        // Cell update: 512 cells (8 jj x 64 b), 2 per thread; C in registers.
        const int par = t & 1;
        #pragma unroll
        for (int e = 0; e < 2; ++e) {
            const int cell = tid + e * NTHR;
            const int b = cell & 63, jj = cell >> 6;
            float gate[4];
            #pragma unroll
            for (int g = 0; g < 4; ++g)
                gate[g] = gsm[(g * 8 + jj) * GLD + b]
                        + gsm[32 * GLD + (g * 8 + jj) * GLD + b]
                        + bias[g * 8 + jj];
            const float Cnew = fsigm(gate[0]) * Creg[e] + fsigm(gate[1]) * ftanh(gate[2]);
            Creg[e] = Cnew;
            const float h = fsigm(gate[3]) * ftanh(Cnew);
            const int bg = nbase + b, jg = j0 + jj;
            out[(size_t)t * (BB * HH) + (size_t)bg * HH + jg] = h;
            const __nv_bfloat16 hi = __float2bfloat16(h);
            const __nv_bfloat16 lo = __float2bfloat16(h - __bfloat162float(hi));
            g_hsplit[(size_t)((par * 2 + 0) * 128 + bg) * HH + jg] = hi;
            g_hsplit[(size_t)((par * 2 + 1) * 128 + bg) * HH + jg] = lo;
        }

        if (t < TT - 1) {
            __syncthreads();
            // Prefetch next step's chunk 0 (pure x) across the barrier.
            stage(vsm_s, t + 1, 0, tid, nbase);
            asm volatile("cp.async.commit_group;");
            if (tid == 0) {
                asm volatile("red.release.gpu.global.add.u32 [%0], %1;"
                             :: "l"(&g_bar), "r"(1u) : "memory");
                const unsigned target = (unsigned)NCTA * (unsigned)(t + 1);
                unsigned v;
                do {
                    asm volatile("ld.acquire.gpu.global.u32 %0, [%1];"
                                 : "=r"(v) : "l"(&g_bar) : "memory");
                } while (v < target);
            }
            __syncthreads();
        }
    }
}

// ---------------------------------------------------------------------------
extern "C" void kernel_launch(void* const* d_in, const int* in_sizes, int n_in,
                              void* d_out, int out_size) {
    (void)in_sizes; (void)n_in; (void)out_size;
    const float* x  = (const float*)d_in[0];
    const float* Wf = (const float*)d_in[1];
    const float* bf = (const float*)d_in[2];
    const float* Wi = (const float*)d_in[3];
    const float* bi = (const float*)d_in[4];
    const float* Wc = (const float*)d_in[5];
    const float* bc = (const float*)d_in[6];
    const float* Wo = (const float*)d_in[7];
    const float* bo = (const float*)d_in[8];
    float* out = (float*)d_out;

    cudaFuncSetAttribute(lstm_wmma, cudaFuncAttributeMaxDynamicSharedMemorySize, SMEM_BYTES);

    pack_W<<<dim3(64, 4), 256>>>(Wf, Wi, Wc, Wo);      // also resets g_bar
    pack_x<<<TT, 256>>>(x);
    lstm_wmma<<<NCTA, NTHR, SMEM_BYTES>>>(bf, bi, bc, bo, out);
}